// round 7
// baseline (speedup 1.0000x reference)
#include <cuda_runtime.h>

// Problem constants
#define N_IMG 64
#define C_IN 96
#define C_EXP 576
#define C_SE 144
#define HW 784
#define HDIM 28

// Scratch (device globals: allocation-free, graph-capturable)
__device__ float g_e[(size_t)N_IMG * C_EXP * HW];     // expand output (0..255 continuous)
__device__ float g_d[(size_t)N_IMG * C_EXP * HW];     // depthwise output (0..255 continuous)
__device__ float g_pool[N_IMG * C_EXP];               // global avg pool of d
__device__ float g_gmul[N_IMG * C_EXP];               // per-(n,c) SE gate multiplier

__device__ __forceinline__ float clamp255(float v) { return fminf(fmaxf(v, 0.f), 255.f); }
__device__ __forceinline__ float hswish(float v) {
    return v * (fminf(fmaxf(v + 3.f, 0.f), 6.f) * (1.f / 6.f));
}

// ---------------------------------------------------------------------------
// K1: expand 1x1 conv as int8 dp4a GEMM  (M=50176 pixels, N=576, K=96)
// x-128 and w_exp are exact int8 -> dp4a accumulation is bit-exact.
// Epilogue: +bias, dequant (S_IN*W_SCALE), hardswish, requant (1/S1, +128).
// ---------------------------------------------------------------------------
__global__ __launch_bounds__(256) void k_expand(const float* __restrict__ x,
                                                const float* __restrict__ w,
                                                const float* __restrict__ bias) {
    __shared__ int As[24][64];   // packed 4 k's per int, [k/4][m]
    __shared__ int Bs[24][64];   // [k/4][oc]
    const int mBase = blockIdx.x * 64;
    const int nBase = blockIdx.y * 64;
    const int tid = threadIdx.x;

    // Load + pack A tile (coalesced over m -> hw)
    for (int i = tid; i < 24 * 64; i += 256) {
        int kp = i >> 6, m = i & 63;
        int gm = mBase + m;
        int n = gm / HW, hw = gm - n * HW;
        const float* xp = x + ((size_t)n * C_IN + kp * 4) * HW + hw;
        int a0 = ((int)(xp[0] - 128.f)) & 0xFF;
        int a1 = ((int)(xp[HW] - 128.f)) & 0xFF;
        int a2 = ((int)(xp[2 * HW] - 128.f)) & 0xFF;
        int a3 = ((int)(xp[3 * HW] - 128.f)) & 0xFF;
        As[kp][m] = a0 | (a1 << 8) | (a2 << 16) | (a3 << 24);
    }
    // Load + pack B tile (coalesced over k)
    for (int i = tid; i < 24 * 64; i += 256) {
        int nn = i / 24, kp = i - nn * 24;
        const float* wp = w + (nBase + nn) * C_IN + kp * 4;
        int b0 = ((int)wp[0]) & 0xFF;
        int b1 = ((int)wp[1]) & 0xFF;
        int b2 = ((int)wp[2]) & 0xFF;
        int b3 = ((int)wp[3]) & 0xFF;
        Bs[kp][nn] = b0 | (b1 << 8) | (b2 << 16) | (b3 << 24);
    }
    __syncthreads();

    const int tx = tid & 15;   // m group
    const int ty = tid >> 4;   // n group
    int acc[4][4];
#pragma unroll
    for (int i = 0; i < 4; i++)
#pragma unroll
        for (int j = 0; j < 4; j++) acc[i][j] = 0;

#pragma unroll
    for (int kp = 0; kp < 24; kp++) {
        int4 a = *(const int4*)&As[kp][tx * 4];
        int4 bb = *(const int4*)&Bs[kp][ty * 4];
        int av[4] = {a.x, a.y, a.z, a.w};
        int bv[4] = {bb.x, bb.y, bb.z, bb.w};
#pragma unroll
        for (int i = 0; i < 4; i++)
#pragma unroll
            for (int j = 0; j < 4; j++)
                acc[i][j] = __dp4a(av[i], bv[j], acc[i][j]);
    }

#pragma unroll
    for (int i = 0; i < 4; i++) {
        int gm = mBase + tx * 4 + i;
        int n = gm / HW, hw = gm - n * HW;
#pragma unroll
        for (int j = 0; j < 4; j++) {
            int oc = nBase + ty * 4 + j;
            float a = (float)acc[i][j] + bias[oc];
            float deq = a * (0.05f * 0.01f);            // S_IN * W_SCALE
            float ev = clamp255(hswish(deq) * 25.f + 128.f);   // 1/S1=25, Z1=128
            g_e[((size_t)n * C_EXP + oc) * HW + hw] = ev;
        }
    }
}

// ---------------------------------------------------------------------------
// K2: depthwise 5x5 (pad 2) + hardswish + requant, fused global-average pool.
// One block per (n,c) plane.
// ---------------------------------------------------------------------------
__global__ __launch_bounds__(256) void k_dw(const float* __restrict__ w,
                                            const float* __restrict__ bias) {
    __shared__ float tile[32][33];
    __shared__ float wgt[25];
    __shared__ float wsum[8];
    const int nc = blockIdx.x;           // n*576 + c
    const int c = nc % C_EXP;
    const int tid = threadIdx.x;
    const float* ep = g_e + (size_t)nc * HW;

    // Load padded plane, pre-shifted by Z1=128 (halo = 0 in shifted domain)
    for (int i = tid; i < 32 * 32; i += 256) {
        int r = i >> 5, col = i & 31;
        int h = r - 2, ww = col - 2;
        float v = 0.f;
        if (h >= 0 && h < HDIM && ww >= 0 && ww < HDIM) v = ep[h * HDIM + ww] - 128.f;
        tile[r][col] = v;
    }
    if (tid < 25) wgt[tid] = w[c * 25 + tid];
    const float bv = bias[c];
    __syncthreads();

    float* dp = g_d + (size_t)nc * HW;
    float lsum = 0.f;
    for (int p = tid; p < HW; p += 256) {
        int h = p / HDIM, ww = p - h * HDIM;
        float acc = bv;
#pragma unroll
        for (int kh = 0; kh < 5; kh++)
#pragma unroll
            for (int kw = 0; kw < 5; kw++)
                acc += tile[h + kh][ww + kw] * wgt[kh * 5 + kw];
        float deq = acc * (0.04f * 0.01f);              // S1 * W_SCALE
        float dv = clamp255(hswish(deq) * 25.f + 128.f);   // 1/S2=25, Z2=128
        dp[p] = dv;
        lsum += dv;
    }
    // Block reduce -> mean
    for (int o = 16; o > 0; o >>= 1) lsum += __shfl_down_sync(0xFFFFFFFFu, lsum, o);
    if ((tid & 31) == 0) wsum[tid >> 5] = lsum;
    __syncthreads();
    if (tid == 0) {
        float t = 0.f;
#pragma unroll
        for (int i = 0; i < 8; i++) t += wsum[i];
        g_pool[nc] = t * (1.f / 784.f);
    }
}

// ---------------------------------------------------------------------------
// K3: squeeze-excitation. One block per image, 576 threads.
// Produces g_gmul[n][c] = g2 * (S_SE2*S2/S_MUL) = hardsigmoid output.
// ---------------------------------------------------------------------------
__global__ __launch_bounds__(576) void k_se(const float* __restrict__ w1,
                                            const float* __restrict__ b1,
                                            const float* __restrict__ w2,
                                            const float* __restrict__ b2) {
    __shared__ float ps[C_EXP];
    __shared__ float g1s[C_SE];
    const int n = blockIdx.x;
    const int tid = threadIdx.x;
    ps[tid] = g_pool[n * C_EXP + tid] - 128.f;          // shift by Z2
    __syncthreads();
    if (tid < C_SE) {
        float acc = b1[tid];
        const float* wr = w1 + tid * C_EXP;
        for (int k = 0; k < C_EXP; k++) acc += ps[k] * wr[k];
        float deq = acc * (0.04f * 0.01f);              // S2 * W_SCALE
        float g1 = clamp255(deq * (float)(1.0 / 0.03) + 128.f);  // 1/S_SE1, Z_SE1
        g1s[tid] = g1 - 128.f;                           // pre-shift for fc2
    }
    __syncthreads();
    {
        float acc = b2[tid];
        const float* wr = w2 + tid * C_SE;
        for (int k = 0; k < C_SE; k++) acc += g1s[k] * wr[k];
        float deq = acc * (0.03f * 0.01f);              // S_SE1 * W_SCALE
        float hsg = fminf(fmaxf(deq + 3.f, 0.f), 6.f) * (1.f / 6.f);
        float g2 = clamp255(hsg * 255.f);                // 1/S_SE2=255, Z_SE2=0
        g_gmul[n * C_EXP + tid] = g2 * (float)(1.0 / 255.0);  // S_SE2*S2/S_MUL
    }
}

// ---------------------------------------------------------------------------
// K4: SE-gate + project 1x1 GEMM (M=50176, N=96, K=576) + residual add.
// gated-128 = clip(gmul*(d-128), -128, 127) is computed in the A-tile load.
// ---------------------------------------------------------------------------
__global__ __launch_bounds__(384) void k_proj(const float* __restrict__ x,
                                              const float* __restrict__ w,
                                              const float* __restrict__ bias,
                                              float* __restrict__ out) {
    __shared__ float As[32][64];   // [k][m]
    __shared__ float Bs[32][96];   // [k][oc]
    const int mBase = blockIdx.x * 64;
    const int tid = threadIdx.x;
    const int tx = tid & 15;       // m group (0..15)
    const int ty = tid >> 4;       // n group (0..23)

    float acc[4][4] = {};
    for (int k0 = 0; k0 < C_EXP; k0 += 32) {
        for (int i = tid; i < 32 * 64; i += 384) {
            int k = i >> 6, m = i & 63;
            int gm = mBase + m;
            int n = gm / HW, hw = gm - n * HW;
            int kk = k0 + k;
            float dv = g_d[((size_t)n * C_EXP + kk) * HW + hw];
            float gv = g_gmul[n * C_EXP + kk];
            // (gated - Z_MUL) = clip(gmul*(d-128)+128, 0,255) - 128
            As[k][m] = fminf(fmaxf(gv * (dv - 128.f), -128.f), 127.f);
        }
        for (int i = tid; i < 32 * 96; i += 384) {
            int nn = i >> 5, k = i & 31;
            Bs[k][nn] = w[nn * C_EXP + k0 + k];
        }
        __syncthreads();
#pragma unroll
        for (int k = 0; k < 32; k++) {
            float4 a = *(const float4*)&As[k][tx * 4];
            float4 bb = *(const float4*)&Bs[k][ty * 4];
            float av[4] = {a.x, a.y, a.z, a.w};
            float bv[4] = {bb.x, bb.y, bb.z, bb.w};
#pragma unroll
            for (int i = 0; i < 4; i++)
#pragma unroll
                for (int j = 0; j < 4; j++)
                    acc[i][j] = fmaf(av[i], bv[j], acc[i][j]);
        }
        __syncthreads();
    }

#pragma unroll
    for (int i = 0; i < 4; i++) {
        int gm = mBase + tx * 4 + i;
        int n = gm / HW, hw = gm - n * HW;
#pragma unroll
        for (int j = 0; j < 4; j++) {
            int oc = ty * 4 + j;
            float a = acc[i][j] + bias[oc];
            float deq = a * (0.04f * 0.01f);            // S_MUL * W_SCALE
            float p = clamp255(deq * 20.f + 128.f);     // 1/S3=20, Z3=128
            size_t idx = ((size_t)n * C_IN + oc) * HW + hw;
            float xv = x[idx];
            // (x-128)*(S_IN/S_OUT) + (p-128)*(S3/S_OUT) + Z_OUT, both ratios = 5/6
            out[idx] = clamp255(((xv - 128.f) + (p - 128.f)) * (0.05f / 0.06f) + 128.f);
        }
    }
}

// ---------------------------------------------------------------------------
extern "C" void kernel_launch(void* const* d_in, const int* in_sizes, int n_in,
                              void* d_out, int out_size) {
    const float* x      = (const float*)d_in[0];
    const float* w_exp  = (const float*)d_in[1];
    const float* b_exp  = (const float*)d_in[2];
    const float* w_dw   = (const float*)d_in[3];
    const float* b_dw   = (const float*)d_in[4];
    const float* w_se1  = (const float*)d_in[5];
    const float* b_se1  = (const float*)d_in[6];
    const float* w_se2  = (const float*)d_in[7];
    const float* b_se2  = (const float*)d_in[8];
    const float* w_proj = (const float*)d_in[9];
    const float* b_proj = (const float*)d_in[10];
    float* out = (float*)d_out;

    (void)in_sizes; (void)n_in; (void)out_size;

    k_expand<<<dim3(784, 9), 256>>>(x, w_exp, b_exp);
    k_dw<<<N_IMG * C_EXP, 256>>>(w_dw, b_dw);
    k_se<<<N_IMG, C_EXP>>>(w_se1, b_se1, w_se2, b_se2);
    k_proj<<<784, 384>>>(x, w_proj, b_proj, out);
}

// round 9
// speedup vs baseline: 1.3660x; 1.3660x over previous
#include <cuda_runtime.h>

// Problem constants
#define N_IMG 64
#define C_IN 96
#define C_EXP 576
#define C_SE 144
#define HW 784
#define HDIM 28

// Scratch (device globals: allocation-free, graph-capturable)
__device__ float g_e[(size_t)N_IMG * C_EXP * HW];     // expand output (0..255 continuous)
__device__ float g_d[(size_t)N_IMG * C_EXP * HW];     // depthwise output (0..255 continuous)
__device__ float g_pool[N_IMG * C_EXP];               // global avg pool of d
__device__ float g_gmul[N_IMG * C_EXP];               // per-(n,c) SE gate multiplier

__device__ __forceinline__ float clamp255(float v) { return fminf(fmaxf(v, 0.f), 255.f); }
__device__ __forceinline__ float hswish(float v) {
    return v * (fminf(fmaxf(v + 3.f, 0.f), 6.f) * (1.f / 6.f));
}

// ---------------------------------------------------------------------------
// K1: expand 1x1 conv as int8 dp4a GEMM  (M=50176 pixels, N=576, K=96)
// x-128 and w_exp are exact int8 -> dp4a accumulation is bit-exact.
// Per-thread m mapping is tx + 16*i so the epilogue stores are coalesced.
// ---------------------------------------------------------------------------
__global__ __launch_bounds__(256) void k_expand(const float* __restrict__ x,
                                                const float* __restrict__ w,
                                                const float* __restrict__ bias) {
    __shared__ int As[24][64];   // packed 4 k's per int, [k/4][m]
    __shared__ int Bs[24][64];   // [k/4][oc]
    const int mBase = blockIdx.x * 64;
    const int nBase = blockIdx.y * 64;
    const int tid = threadIdx.x;
    const int n0 = mBase / HW;
    const int hw0 = mBase - n0 * HW;

    // Load + pack A tile (coalesced over m -> hw)
    for (int i = tid; i < 24 * 64; i += 256) {
        int kp = i >> 6, m = i & 63;
        int hw = hw0 + m, n = n0;
        if (hw >= HW) { hw -= HW; n++; }
        const float* xp = x + ((size_t)(n * C_IN + kp * 4)) * HW + hw;
        int a0 = ((int)(xp[0] - 128.f)) & 0xFF;
        int a1 = ((int)(xp[HW] - 128.f)) & 0xFF;
        int a2 = ((int)(xp[2 * HW] - 128.f)) & 0xFF;
        int a3 = ((int)(xp[3 * HW] - 128.f)) & 0xFF;
        As[kp][m] = a0 | (a1 << 8) | (a2 << 16) | (a3 << 24);
    }
    // Load + pack B tile
    for (int i = tid; i < 24 * 64; i += 256) {
        int nn = i / 24, kp = i - nn * 24;
        const float4 wv = *(const float4*)(w + (nBase + nn) * C_IN + kp * 4);
        int b0 = ((int)wv.x) & 0xFF;
        int b1 = ((int)wv.y) & 0xFF;
        int b2 = ((int)wv.z) & 0xFF;
        int b3 = ((int)wv.w) & 0xFF;
        Bs[kp][nn] = b0 | (b1 << 8) | (b2 << 16) | (b3 << 24);
    }
    __syncthreads();

    const int tx = tid & 15;   // m lane
    const int ty = tid >> 4;   // n group
    int acc[4][4];
#pragma unroll
    for (int i = 0; i < 4; i++)
#pragma unroll
        for (int j = 0; j < 4; j++) acc[i][j] = 0;

#pragma unroll
    for (int kp = 0; kp < 24; kp++) {
        int av[4];
#pragma unroll
        for (int i = 0; i < 4; i++) av[i] = As[kp][tx + 16 * i];
        int4 bb = *(const int4*)&Bs[kp][ty * 4];
        int bv[4] = {bb.x, bb.y, bb.z, bb.w};
#pragma unroll
        for (int i = 0; i < 4; i++)
#pragma unroll
            for (int j = 0; j < 4; j++)
                acc[i][j] = __dp4a(av[i], bv[j], acc[i][j]);
    }

#pragma unroll
    for (int i = 0; i < 4; i++) {
        int m = tx + 16 * i;
        int hw = hw0 + m, n = n0;
        if (hw >= HW) { hw -= HW; n++; }
#pragma unroll
        for (int j = 0; j < 4; j++) {
            int oc = nBase + ty * 4 + j;
            float a = (float)acc[i][j] + bias[oc];
            float deq = a * (0.05f * 0.01f);                   // S_IN * W_SCALE
            float ev = clamp255(hswish(deq) * 25.f + 128.f);   // 1/S1=25, Z1=128
            g_e[((size_t)(n * C_EXP + oc)) * HW + hw] = ev;
        }
    }
}

// ---------------------------------------------------------------------------
// K2: depthwise 5x5 (pad 2) + hardswish + requant, fused global-average pool.
// One block per (n,c) plane; 112 active threads compute 7 horizontal outputs
// each with a register sliding window (55 LDS : 175 FMA). Output staged in
// smem and stored with coalesced float4.
// ---------------------------------------------------------------------------
__global__ __launch_bounds__(128) void k_dw(const float* __restrict__ w,
                                            const float* __restrict__ bias) {
    __shared__ float tile[32][33];
    __shared__ __align__(16) float outp[HW];
    __shared__ float wgt[25];
    __shared__ float wsum[4];
    const int nc = blockIdx.x;           // n*576 + c
    const int c = nc % C_EXP;
    const int tid = threadIdx.x;
    const float* ep = g_e + (size_t)nc * HW;

    // Load padded plane, pre-shifted by Z1=128 (halo = 0 in shifted domain)
    for (int i = tid; i < 32 * 32; i += 128) {
        int r = i >> 5, col = i & 31;
        int h = r - 2, ww = col - 2;
        float v = 0.f;
        if (h >= 0 && h < HDIM && ww >= 0 && ww < HDIM) v = ep[h * HDIM + ww] - 128.f;
        tile[r][col] = v;
    }
    if (tid < 25) wgt[tid] = w[c * 25 + tid];
    const float bv = bias[c];
    __syncthreads();

    float lsum = 0.f;
    if (tid < 112) {
        const int row = tid >> 2;          // 0..27
        const int wb = (tid & 3) * 7;      // 0,7,14,21
        float acc[7];
#pragma unroll
        for (int j = 0; j < 7; j++) acc[j] = bv;
#pragma unroll
        for (int kh = 0; kh < 5; kh++) {
            float rr[11];
#pragma unroll
            for (int q = 0; q < 11; q++) rr[q] = tile[row + kh][wb + q];
#pragma unroll
            for (int kw = 0; kw < 5; kw++) {
                float wv = wgt[kh * 5 + kw];
#pragma unroll
                for (int j = 0; j < 7; j++) acc[j] = fmaf(rr[j + kw], wv, acc[j]);
            }
        }
#pragma unroll
        for (int j = 0; j < 7; j++) {
            float deq = acc[j] * (0.04f * 0.01f);                // S1 * W_SCALE
            float dv = clamp255(hswish(deq) * 25.f + 128.f);     // 1/S2=25, Z2=128
            outp[row * HDIM + wb + j] = dv;
            lsum += dv;
        }
    }
    // Block reduce -> mean
    for (int o = 16; o > 0; o >>= 1) lsum += __shfl_down_sync(0xFFFFFFFFu, lsum, o);
    if ((tid & 31) == 0) wsum[tid >> 5] = lsum;
    __syncthreads();

    float* dp = g_d + (size_t)nc * HW;
    for (int i = tid; i < HW / 4; i += 128)
        *(float4*)(dp + 4 * i) = *(const float4*)(outp + 4 * i);
    if (tid == 0)
        g_pool[nc] = (wsum[0] + wsum[1] + wsum[2] + wsum[3]) * (1.f / 784.f);
}

// ---------------------------------------------------------------------------
// K3: squeeze-excitation. One block per image, 256 threads, warp-per-output
// with coalesced weight reads + shfl reduction.
// ---------------------------------------------------------------------------
__global__ __launch_bounds__(256) void k_se(const float* __restrict__ w1,
                                            const float* __restrict__ b1,
                                            const float* __restrict__ w2,
                                            const float* __restrict__ b2) {
    __shared__ float ps[C_EXP];
    __shared__ float g1s[C_SE];
    const int n = blockIdx.x;
    const int tid = threadIdx.x;
    const int wid = tid >> 5;
    const int lane = tid & 31;

    for (int i = tid; i < C_EXP; i += 256)
        ps[i] = g_pool[n * C_EXP + i] - 128.f;            // shift by Z2
    __syncthreads();

    // fc1: 144 outputs, 8 warps -> 18 each
    for (int o = wid; o < C_SE; o += 8) {
        const float* wr = w1 + o * C_EXP;
        float acc = 0.f;
        for (int k = lane; k < C_EXP; k += 32) acc += ps[k] * wr[k];
        for (int off = 16; off > 0; off >>= 1) acc += __shfl_down_sync(0xFFFFFFFFu, acc, off);
        if (lane == 0) {
            acc += b1[o];
            float deq = acc * (0.04f * 0.01f);            // S2 * W_SCALE
            float g1 = clamp255(deq * (float)(1.0 / 0.03) + 128.f);
            g1s[o] = g1 - 128.f;
        }
    }
    __syncthreads();

    // fc2: 576 outputs, 8 warps -> 72 each
    for (int o = wid; o < C_EXP; o += 8) {
        const float* wr = w2 + o * C_SE;
        float acc = 0.f;
        for (int k = lane; k < C_SE; k += 32) acc += g1s[k] * wr[k];
        for (int off = 16; off > 0; off >>= 1) acc += __shfl_down_sync(0xFFFFFFFFu, acc, off);
        if (lane == 0) {
            acc += b2[o];
            float deq = acc * (0.03f * 0.01f);            // S_SE1 * W_SCALE
            float hsg = fminf(fmaxf(deq + 3.f, 0.f), 6.f) * (1.f / 6.f);
            float g2 = clamp255(hsg * 255.f);             // 1/S_SE2=255
            g_gmul[n * C_EXP + o] = g2 * (float)(1.0 / 255.0);  // S_SE2*S2/S_MUL
        }
    }
}

// ---------------------------------------------------------------------------
// K4: SE-gate + project 1x1 GEMM (M=50176, N=96, K=576) + residual add.
// A = clip(gmul*(d-128), -128, 127) is continuous; split exactly as
// a ~= ah + al/128 with ah, al int8 (residual <= 1/256) and run two dp4a
// accumulations. 4x fewer MAC instructions and 4x less smem than fp32 FFMA.
// ---------------------------------------------------------------------------
__global__ __launch_bounds__(256) void k_proj(const float* __restrict__ x,
                                              const float* __restrict__ w,
                                              const float* __restrict__ bias,
                                              float* __restrict__ out) {
    __shared__ int AsH[8][64];   // hi bytes, 4 k's packed
    __shared__ int AsL[8][64];   // lo bytes (residual*128)
    __shared__ int Bs[8][96];
    const int mBase = blockIdx.x * 64;
    const int tid = threadIdx.x;
    const int tx = tid & 15;     // m lane
    const int ty = tid >> 4;     // n group: oc = ty*6 + j
    const int n0 = mBase / HW;
    const int hw0 = mBase - n0 * HW;

    int accH[4][6] = {};
    int accL[4][6] = {};

    for (int k0 = 0; k0 < C_EXP; k0 += 32) {
        // A pack: 8 kp x 64 m = 512 ints, 2 per thread, 4 elements each
#pragma unroll
        for (int t = 0; t < 2; t++) {
            int idx = tid + 256 * t;
            int kp = idx >> 6, m = idx & 63;
            int hw = hw0 + m, n = n0;
            if (hw >= HW) { hw -= HW; n++; }
            int base = n * C_EXP + k0 + kp * 4;
            int ph = 0, pl = 0;
#pragma unroll
            for (int u = 0; u < 4; u++) {
                float dv = g_d[(size_t)(base + u) * HW + hw];
                float gv = g_gmul[base + u];
                float a = fminf(fmaxf(gv * (dv - 128.f), -128.f), 127.f);
                float ahf = rintf(a);
                int ah = (int)ahf;
                int al = (int)rintf((a - ahf) * 128.f);
                ph |= (ah & 0xFF) << (8 * u);
                pl |= (al & 0xFF) << (8 * u);
            }
            AsH[kp][m] = ph;
            AsL[kp][m] = pl;
        }
        // B pack: 8 kp x 96 nn = 768 ints, 3 per thread
#pragma unroll
        for (int t = 0; t < 3; t++) {
            int idx = tid + 256 * t;
            int kp = idx & 7, nn = idx >> 3;
            const float4 wv = *(const float4*)(w + nn * C_EXP + k0 + kp * 4);
            int b0 = ((int)wv.x) & 0xFF;
            int b1 = ((int)wv.y) & 0xFF;
            int b2 = ((int)wv.z) & 0xFF;
            int b3 = ((int)wv.w) & 0xFF;
            Bs[kp][nn] = b0 | (b1 << 8) | (b2 << 16) | (b3 << 24);
        }
        __syncthreads();

#pragma unroll
        for (int kp = 0; kp < 8; kp++) {
            int avh[4], avl[4], bv[6];
#pragma unroll
            for (int i = 0; i < 4; i++) {
                avh[i] = AsH[kp][tx + 16 * i];
                avl[i] = AsL[kp][tx + 16 * i];
            }
#pragma unroll
            for (int j = 0; j < 6; j++) bv[j] = Bs[kp][ty * 6 + j];
#pragma unroll
            for (int i = 0; i < 4; i++)
#pragma unroll
                for (int j = 0; j < 6; j++) {
                    accH[i][j] = __dp4a(avh[i], bv[j], accH[i][j]);
                    accL[i][j] = __dp4a(avl[i], bv[j], accL[i][j]);
                }
        }
        __syncthreads();
    }

#pragma unroll
    for (int i = 0; i < 4; i++) {
        int m = tx + 16 * i;
        int hw = hw0 + m, n = n0;
        if (hw >= HW) { hw -= HW; n++; }
#pragma unroll
        for (int j = 0; j < 6; j++) {
            int oc = ty * 6 + j;
            float a = (float)accH[i][j] + (float)accL[i][j] * 0.0078125f + bias[oc];
            float deq = a * (0.04f * 0.01f);              // S_MUL * W_SCALE
            float p = clamp255(deq * 20.f + 128.f);       // 1/S3=20, Z3=128
            size_t idx = ((size_t)(n * C_IN + oc)) * HW + hw;
            float xv = x[idx];
            // (x-128)*(S_IN/S_OUT) + (p-128)*(S3/S_OUT) + Z_OUT, both ratios = 5/6
            out[idx] = clamp255(((xv - 128.f) + (p - 128.f)) * (0.05f / 0.06f) + 128.f);
        }
    }
}

// ---------------------------------------------------------------------------
extern "C" void kernel_launch(void* const* d_in, const int* in_sizes, int n_in,
                              void* d_out, int out_size) {
    const float* x      = (const float*)d_in[0];
    const float* w_exp  = (const float*)d_in[1];
    const float* b_exp  = (const float*)d_in[2];
    const float* w_dw   = (const float*)d_in[3];
    const float* b_dw   = (const float*)d_in[4];
    const float* w_se1  = (const float*)d_in[5];
    const float* b_se1  = (const float*)d_in[6];
    const float* w_se2  = (const float*)d_in[7];
    const float* b_se2  = (const float*)d_in[8];
    const float* w_proj = (const float*)d_in[9];
    const float* b_proj = (const float*)d_in[10];
    float* out = (float*)d_out;

    (void)in_sizes; (void)n_in; (void)out_size;

    k_expand<<<dim3(784, 9), 256>>>(x, w_exp, b_exp);
    k_dw<<<N_IMG * C_EXP, 128>>>(w_dw, b_dw);
    k_se<<<N_IMG, 256>>>(w_se1, b_se1, w_se2, b_se2);
    k_proj<<<784, 256>>>(x, w_proj, b_proj, out);
}

// round 10
// speedup vs baseline: 1.6563x; 1.2125x over previous
#include <cuda_runtime.h>
#include <cstdint>

// Problem constants
#define N_IMG 64
#define C_IN 96
#define C_EXP 576
#define C_SE 144
#define HW 784
#define HDIM 28

// Scratch (device globals: allocation-free, graph-capturable)
__device__ float g_e[(size_t)N_IMG * C_EXP * HW];   // expand output - 128 (continuous)
__device__ float g_d[(size_t)N_IMG * C_EXP * HW];   // depthwise output (0..255 continuous)
__device__ float g_pool[N_IMG * C_EXP];             // global avg pool of d
__device__ float g_gmul[N_IMG * C_EXP];             // per-(n,c) SE gate multiplier

__device__ int g_xp[N_IMG * 24 * HW];               // packed x-128 int8x4, [(n*24+kp)*HW+hw]
__device__ int g_wpe[24 * C_EXP];                   // packed w_exp, [kp*576+oc]
__device__ int g_wpp[144 * C_IN];                   // packed w_proj, [kp*96+oc]
__device__ int g_ah[(size_t)N_IMG * 144 * HW];      // gated A hi bytes, [(n*144+kp)*HW+hw]
__device__ int g_al[(size_t)N_IMG * 144 * HW];      // gated A lo bytes (residual*128)

__device__ __forceinline__ float clamp255(float v) { return fminf(fmaxf(v, 0.f), 255.f); }
__device__ __forceinline__ float hswish(float v) {
    return v * (fminf(fmaxf(v + 3.f, 0.f), 6.f) * (1.f / 6.f));
}

#define CPA4(dst_u32, src_ptr) \
    asm volatile("cp.async.ca.shared.global [%0], [%1], 4;" ::"r"(dst_u32), "l"(src_ptr))

// ---------------------------------------------------------------------------
// K0: one-time packing of x (int8x4) and both GEMM weight matrices into
// dp4a-friendly int32 layouts.
// ---------------------------------------------------------------------------
__global__ __launch_bounds__(256) void k_pack(const float* __restrict__ x,
                                              const float* __restrict__ we,
                                              const float* __restrict__ wp) {
    const int i = blockIdx.x * 256 + threadIdx.x;
    const int NX = N_IMG * 24 * HW;          // 1204224
    const int NWE = 24 * C_EXP;              // 13824
    const int NWP = 144 * C_IN;              // 13824
    if (i < NX) {
        int q = i / HW, hw = i - q * HW;     // q = n*24+kp
        int n = q / 24, kp = q - n * 24;
        const float* xp = x + ((size_t)(n * C_IN + kp * 4)) * HW + hw;
        int a0 = ((int)(xp[0] - 128.f)) & 0xFF;
        int a1 = ((int)(xp[HW] - 128.f)) & 0xFF;
        int a2 = ((int)(xp[2 * HW] - 128.f)) & 0xFF;
        int a3 = ((int)(xp[3 * HW] - 128.f)) & 0xFF;
        g_xp[i] = a0 | (a1 << 8) | (a2 << 16) | (a3 << 24);
    } else if (i < NX + NWE) {
        int j = i - NX;                      // j = kp*576+oc
        int kp = j / C_EXP, oc = j - kp * C_EXP;
        const float* w = we + oc * C_IN + kp * 4;
        int b0 = ((int)w[0]) & 0xFF, b1 = ((int)w[1]) & 0xFF;
        int b2 = ((int)w[2]) & 0xFF, b3 = ((int)w[3]) & 0xFF;
        g_wpe[j] = b0 | (b1 << 8) | (b2 << 16) | (b3 << 24);
    } else if (i < NX + NWE + NWP) {
        int j = i - NX - NWE;                // j = kp*96+oc
        int kp = j / C_IN, oc = j - kp * C_IN;
        const float* w = wp + oc * C_EXP + kp * 4;
        int b0 = ((int)w[0]) & 0xFF, b1 = ((int)w[1]) & 0xFF;
        int b2 = ((int)w[2]) & 0xFF, b3 = ((int)w[3]) & 0xFF;
        g_wpp[j] = b0 | (b1 << 8) | (b2 << 16) | (b3 << 24);
    }
}

// ---------------------------------------------------------------------------
// K1: expand 1x1 conv as int8 dp4a GEMM (M=50176, N=576, K=96). A and B are
// pre-packed; loads are straight int copies. Stores e-128 (shifted domain).
// ---------------------------------------------------------------------------
__global__ __launch_bounds__(256) void k_expand(const float* __restrict__ bias) {
    __shared__ int As[24][64];   // [kp][m]
    __shared__ int Bs[24][64];   // [kp][oc]
    const int mBase = blockIdx.x * 64;
    const int nBase = blockIdx.y * 64;
    const int tid = threadIdx.x;
    const int n0 = mBase / HW;
    const int hw0 = mBase - n0 * HW;

    for (int i = tid; i < 24 * 64; i += 256) {
        int kp = i >> 6, m = i & 63;
        int hw = hw0 + m, n = n0;
        if (hw >= HW) { hw -= HW; n++; }
        As[kp][m] = g_xp[(n * 24 + kp) * HW + hw];
    }
    for (int i = tid; i < 24 * 64; i += 256) {
        int kp = i >> 6, oc = i & 63;
        Bs[kp][oc] = g_wpe[kp * C_EXP + nBase + oc];
    }
    __syncthreads();

    const int tx = tid & 15;   // m lane
    const int ty = tid >> 4;   // n group
    int acc[4][4];
#pragma unroll
    for (int i = 0; i < 4; i++)
#pragma unroll
        for (int j = 0; j < 4; j++) acc[i][j] = 0;

#pragma unroll
    for (int kp = 0; kp < 24; kp++) {
        int av[4];
#pragma unroll
        for (int i = 0; i < 4; i++) av[i] = As[kp][tx + 16 * i];
        int4 bb = *(const int4*)&Bs[kp][ty * 4];
        int bv[4] = {bb.x, bb.y, bb.z, bb.w};
#pragma unroll
        for (int i = 0; i < 4; i++)
#pragma unroll
            for (int j = 0; j < 4; j++)
                acc[i][j] = __dp4a(av[i], bv[j], acc[i][j]);
    }

#pragma unroll
    for (int i = 0; i < 4; i++) {
        int m = tx + 16 * i;
        int hw = hw0 + m, n = n0;
        if (hw >= HW) { hw -= HW; n++; }
#pragma unroll
        for (int j = 0; j < 4; j++) {
            int oc = nBase + ty * 4 + j;
            float a = (float)acc[i][j] + bias[oc];
            float deq = a * (0.05f * 0.01f);                   // S_IN * W_SCALE
            float ev = clamp255(hswish(deq) * 25.f + 128.f);   // 1/S1=25, Z1=128
            g_e[((size_t)(n * C_EXP + oc)) * HW + hw] = ev - 128.f;  // pre-shifted
        }
    }
}

// ---------------------------------------------------------------------------
// K2: depthwise 5x5 (pad 2) + hardswish + requant, fused global-average pool.
// Plane loaded with fully coalesced float4 (196 vectors), scattered into the
// padded tile. 112 threads compute 7 horizontal outputs each.
// ---------------------------------------------------------------------------
__global__ __launch_bounds__(128) void k_dw(const float* __restrict__ w,
                                            const float* __restrict__ bias) {
    __shared__ float tile[32][33];
    __shared__ __align__(16) float outp[HW];
    __shared__ float wgt[25];
    __shared__ float wsum[4];
    const int nc = blockIdx.x;           // n*576 + c
    const int c = nc % C_EXP;
    const int tid = threadIdx.x;
    const float* ep = g_e + (size_t)nc * HW;   // already e-128 (halo = 0)

    // zero padded tile
    for (int i = tid; i < 32 * 33; i += 128) ((float*)tile)[i] = 0.f;
    if (tid < 25) wgt[tid] = w[c * 25 + tid];
    const float bv = bias[c];
    __syncthreads();

    // coalesced float4 load + scatter into padded tile
    for (int t = tid; t < 196; t += 128) {
        float4 v = ((const float4*)ep)[t];
        int lin = 4 * t;
        int r = lin / HDIM;
        int col = lin - HDIM * r;
        float vv[4] = {v.x, v.y, v.z, v.w};
#pragma unroll
        for (int u = 0; u < 4; u++) {
            tile[r + 2][col + 2] = vv[u];
            col++;
            if (col == HDIM) { col = 0; r++; }
        }
    }
    __syncthreads();

    float lsum = 0.f;
    if (tid < 112) {
        const int row = tid >> 2;          // 0..27
        const int wb = (tid & 3) * 7;      // 0,7,14,21
        float acc[7];
#pragma unroll
        for (int j = 0; j < 7; j++) acc[j] = bv;
#pragma unroll
        for (int kh = 0; kh < 5; kh++) {
            float rr[11];
#pragma unroll
            for (int q = 0; q < 11; q++) rr[q] = tile[row + kh][wb + q];
#pragma unroll
            for (int kw = 0; kw < 5; kw++) {
                float wv = wgt[kh * 5 + kw];
#pragma unroll
                for (int j = 0; j < 7; j++) acc[j] = fmaf(rr[j + kw], wv, acc[j]);
            }
        }
#pragma unroll
        for (int j = 0; j < 7; j++) {
            float deq = acc[j] * (0.04f * 0.01f);                // S1 * W_SCALE
            float dv = clamp255(hswish(deq) * 25.f + 128.f);     // 1/S2=25, Z2=128
            outp[row * HDIM + wb + j] = dv;
            lsum += dv;
        }
    }
    for (int o = 16; o > 0; o >>= 1) lsum += __shfl_down_sync(0xFFFFFFFFu, lsum, o);
    if ((tid & 31) == 0) wsum[tid >> 5] = lsum;
    __syncthreads();

    float* dp = g_d + (size_t)nc * HW;
    for (int i = tid; i < HW / 4; i += 128)
        *(float4*)(dp + 4 * i) = *(const float4*)(outp + 4 * i);
    if (tid == 0)
        g_pool[nc] = (wsum[0] + wsum[1] + wsum[2] + wsum[3]) * (1.f / 784.f);
}

// ---------------------------------------------------------------------------
// K3: squeeze-excitation. One block per image, warp-per-output.
// ---------------------------------------------------------------------------
__global__ __launch_bounds__(256) void k_se(const float* __restrict__ w1,
                                            const float* __restrict__ b1,
                                            const float* __restrict__ w2,
                                            const float* __restrict__ b2) {
    __shared__ float ps[C_EXP];
    __shared__ float g1s[C_SE];
    const int n = blockIdx.x;
    const int tid = threadIdx.x;
    const int wid = tid >> 5;
    const int lane = tid & 31;

    for (int i = tid; i < C_EXP; i += 256)
        ps[i] = g_pool[n * C_EXP + i] - 128.f;
    __syncthreads();

    for (int o = wid; o < C_SE; o += 8) {
        const float* wr = w1 + o * C_EXP;
        float acc = 0.f;
        for (int k = lane; k < C_EXP; k += 32) acc += ps[k] * wr[k];
        for (int off = 16; off > 0; off >>= 1) acc += __shfl_down_sync(0xFFFFFFFFu, acc, off);
        if (lane == 0) {
            acc += b1[o];
            float deq = acc * (0.04f * 0.01f);
            float g1 = clamp255(deq * (float)(1.0 / 0.03) + 128.f);
            g1s[o] = g1 - 128.f;
        }
    }
    __syncthreads();

    for (int o = wid; o < C_EXP; o += 8) {
        const float* wr = w2 + o * C_SE;
        float acc = 0.f;
        for (int k = lane; k < C_SE; k += 32) acc += g1s[k] * wr[k];
        for (int off = 16; off > 0; off >>= 1) acc += __shfl_down_sync(0xFFFFFFFFu, acc, off);
        if (lane == 0) {
            acc += b2[o];
            float deq = acc * (0.03f * 0.01f);
            float hsg = fminf(fmaxf(deq + 3.f, 0.f), 6.f) * (1.f / 6.f);
            float g2 = clamp255(hsg * 255.f);
            g_gmul[n * C_EXP + o] = g2 * (float)(1.0 / 255.0);
        }
    }
}

// ---------------------------------------------------------------------------
// K3.5: build the packed gated A matrix for the project GEMM.
// a = clip(gmul*(d-128),-128,127) ~= ah + al/128 exact to 1/256.
// One block per (n,kp) row: 196 threads x 4 pixels, float4 in, int4 out.
// ---------------------------------------------------------------------------
__global__ __launch_bounds__(224) void k_gate() {
    const int b = blockIdx.x;              // n*144 + kp
    const int n = b / 144, kp = b - n * 144;
    const int t = threadIdx.x;
    if (t >= 196) return;
    const int hw = 4 * t;
    const float* dbase = g_d + ((size_t)(n * C_EXP + kp * 4)) * HW + hw;
    float gm[4];
    float4 dv[4];
#pragma unroll
    for (int u = 0; u < 4; u++) {
        gm[u] = g_gmul[n * C_EXP + kp * 4 + u];
        dv[u] = *(const float4*)(dbase + (size_t)u * HW);
    }
    int outH[4], outL[4];
#pragma unroll
    for (int e = 0; e < 4; e++) {
        int ph = 0, pl = 0;
#pragma unroll
        for (int u = 0; u < 4; u++) {
            float d = (&dv[u].x)[e];
            float a = fminf(fmaxf(gm[u] * (d - 128.f), -128.f), 127.f);
            float ahf = rintf(a);
            int ah = (int)ahf;
            int al = (int)rintf((a - ahf) * 128.f);
            ph |= (ah & 0xFF) << (8 * u);
            pl |= (al & 0xFF) << (8 * u);
        }
        outH[e] = ph; outL[e] = pl;
    }
    *(int4*)(g_ah + (size_t)b * HW + hw) = make_int4(outH[0], outH[1], outH[2], outH[3]);
    *(int4*)(g_al + (size_t)b * HW + hw) = make_int4(outL[0], outL[1], outL[2], outL[3]);
}

// ---------------------------------------------------------------------------
// K4: project 1x1 GEMM (M=50176, N=96, K=576) + residual add.
// 128 threads, tile 64m x 48oc (grid 784 x 2). B fully resident in smem,
// A (hi/lo) streamed via cp.async 2-stage double buffer. 9 K-tiles of 64.
// ---------------------------------------------------------------------------
__global__ __launch_bounds__(128) void k_proj(const float* __restrict__ x,
                                              const float* __restrict__ bias,
                                              float* __restrict__ out) {
    __shared__ int Bs[144 * 48];           // [kp][oc]  27.6 KB
    __shared__ int AsH[2][16 * 64];        // [buf][kp][m] 8 KB
    __shared__ int AsL[2][16 * 64];        // 8 KB
    const int mBase = blockIdx.x * 64;
    const int ocBase = blockIdx.y * 48;
    const int tid = threadIdx.x;
    const int tx = tid & 15;               // m lane: m = tx + 16*i
    const int ty = tid >> 4;               // 0..7: oc = ocBase + ty*6 + j
    const int n0 = mBase / HW;
    const int hw0 = mBase - n0 * HW;

    // Resident B
    for (int i = tid; i < 144 * 48; i += 128) {
        int kp = i / 48, oc = i - kp * 48;
        Bs[i] = g_wpp[kp * C_IN + ocBase + oc];
    }

    // Per-thread A source offsets (8 (kp,m) pairs per tile)
    int pOff[8];
#pragma unroll
    for (int p = 0; p < 8; p++) {
        int idx = tid + 128 * p;
        int kp = idx >> 6, m = idx & 63;
        int hw = hw0 + m, n = n0;
        if (hw >= HW) { hw -= HW; n++; }
        pOff[p] = (n * 144 + kp) * HW + hw;
    }
    const unsigned sH = (unsigned)__cvta_generic_to_shared(&AsH[0][0]);
    const unsigned sL = (unsigned)__cvta_generic_to_shared(&AsL[0][0]);

    // Prime tile 0
#pragma unroll
    for (int p = 0; p < 8; p++) {
        unsigned d = (tid + 128 * p) * 4u;
        CPA4(sH + d, g_ah + pOff[p]);
        CPA4(sL + d, g_al + pOff[p]);
    }
    asm volatile("cp.async.commit_group;");

    int accH[4][6] = {};
    int accL[4][6] = {};

    for (int t = 0; t < 9; t++) {
        const int buf = t & 1;
        if (t < 8) {
            const int nbuf = buf ^ 1;
            const int adv = (t + 1) * 16 * HW;
#pragma unroll
            for (int p = 0; p < 8; p++) {
                unsigned d = (nbuf * 1024 + tid + 128 * p) * 4u;
                CPA4(sH + d, g_ah + pOff[p] + adv);
                CPA4(sL + d, g_al + pOff[p] + adv);
            }
            asm volatile("cp.async.commit_group;");
            asm volatile("cp.async.wait_group 1;");
        } else {
            asm volatile("cp.async.wait_group 0;");
        }
        __syncthreads();

        const int* AH = AsH[buf];
        const int* AL = AsL[buf];
        const int kbase = 16 * t;
#pragma unroll
        for (int kp = 0; kp < 16; kp++) {
            int avh[4], avl[4], bv[6];
#pragma unroll
            for (int i = 0; i < 4; i++) {
                avh[i] = AH[kp * 64 + tx + 16 * i];
                avl[i] = AL[kp * 64 + tx + 16 * i];
            }
#pragma unroll
            for (int j = 0; j < 6; j++) bv[j] = Bs[(kbase + kp) * 48 + ty * 6 + j];
#pragma unroll
            for (int i = 0; i < 4; i++)
#pragma unroll
                for (int j = 0; j < 6; j++) {
                    accH[i][j] = __dp4a(avh[i], bv[j], accH[i][j]);
                    accL[i][j] = __dp4a(avl[i], bv[j], accL[i][j]);
                }
        }
        __syncthreads();
    }

#pragma unroll
    for (int i = 0; i < 4; i++) {
        int m = tx + 16 * i;
        int hw = hw0 + m, n = n0;
        if (hw >= HW) { hw -= HW; n++; }
#pragma unroll
        for (int j = 0; j < 6; j++) {
            int oc = ocBase + ty * 6 + j;
            float a = (float)accH[i][j] + (float)accL[i][j] * 0.0078125f + bias[oc];
            float deq = a * (0.04f * 0.01f);              // S_MUL * W_SCALE
            float p = clamp255(deq * 20.f + 128.f);       // 1/S3=20, Z3=128
            size_t idx = ((size_t)(n * C_IN + oc)) * HW + hw;
            float xv = x[idx];
            // (x-128)*(S_IN/S_OUT) + (p-128)*(S3/S_OUT) + Z_OUT, both ratios = 5/6
            out[idx] = clamp255(((xv - 128.f) + (p - 128.f)) * (0.05f / 0.06f) + 128.f);
        }
    }
}

// ---------------------------------------------------------------------------
extern "C" void kernel_launch(void* const* d_in, const int* in_sizes, int n_in,
                              void* d_out, int out_size) {
    const float* x      = (const float*)d_in[0];
    const float* w_exp  = (const float*)d_in[1];
    const float* b_exp  = (const float*)d_in[2];
    const float* w_dw   = (const float*)d_in[3];
    const float* b_dw   = (const float*)d_in[4];
    const float* w_se1  = (const float*)d_in[5];
    const float* b_se1  = (const float*)d_in[6];
    const float* w_se2  = (const float*)d_in[7];
    const float* b_se2  = (const float*)d_in[8];
    const float* w_proj = (const float*)d_in[9];
    const float* b_proj = (const float*)d_in[10];
    float* out = (float*)d_out;

    (void)in_sizes; (void)n_in; (void)out_size;

    const int PACK_TOTAL = N_IMG * 24 * HW + 24 * C_EXP + 144 * C_IN;
    k_pack<<<(PACK_TOTAL + 255) / 256, 256>>>(x, w_exp, w_proj);
    k_expand<<<dim3(784, 9), 256>>>(b_exp);
    k_dw<<<N_IMG * C_EXP, 128>>>(w_dw, b_dw);
    k_se<<<N_IMG, 256>>>(w_se1, b_se1, w_se2, b_se2);
    k_gate<<<N_IMG * 144, 224>>>();
    k_proj<<<dim3(784, 2), 128>>>(x, b_proj, out);
}

// round 11
// speedup vs baseline: 2.4865x; 1.5012x over previous
#include <cuda_runtime.h>
#include <cstdint>

// Problem constants
#define N_IMG 64
#define C_IN 96
#define C_EXP 576
#define C_SE 144
#define HW 784
#define HDIM 28

// Scratch (device globals: allocation-free, graph-capturable)
__device__ float g_e[(size_t)N_IMG * C_EXP * HW];   // expand output - 128 (continuous)
__device__ float g_d[(size_t)N_IMG * C_EXP * HW];   // depthwise output - 128 (continuous)
__device__ float g_pool[N_IMG * C_EXP];             // global avg pool of (d-128)
__device__ float g_g1[N_IMG * C_SE];                // SE fc1 output - 128
__device__ float g_gmul[N_IMG * C_EXP];             // per-(n,c) SE gate multiplier

__device__ int g_xp[N_IMG * 24 * HW];               // packed x-128 int8x4, [(n*24+kp)*HW+hw]
__device__ int g_wpe[24 * C_EXP];                   // packed w_exp, [kp*576+oc]
__device__ int g_wpp[144 * C_IN];                   // packed w_proj, [kp*96+oc]
__device__ int g_ah[(size_t)N_IMG * 144 * HW];      // gated A hi bytes, [(n*144+kp)*HW+hw]
__device__ int g_al[(size_t)N_IMG * 144 * HW];      // gated A lo bytes (residual*128)

__device__ __forceinline__ float clamp255(float v) { return fminf(fmaxf(v, 0.f), 255.f); }
__device__ __forceinline__ float hswish(float v) {
    return v * (fminf(fmaxf(v + 3.f, 0.f), 6.f) * (1.f / 6.f));
}

#define CPA4(dst_u32, src_ptr) \
    asm volatile("cp.async.ca.shared.global [%0], [%1], 4;" ::"r"(dst_u32), "l"(src_ptr))

// ---------------------------------------------------------------------------
// K0: one-time packing of x (int8x4) and both GEMM weight matrices into
// dp4a-friendly int32 layouts.
// ---------------------------------------------------------------------------
__global__ __launch_bounds__(256) void k_pack(const float* __restrict__ x,
                                              const float* __restrict__ we,
                                              const float* __restrict__ wp) {
    const int i = blockIdx.x * 256 + threadIdx.x;
    const int NX = N_IMG * 24 * HW;          // 1204224
    const int NWE = 24 * C_EXP;              // 13824
    const int NWP = 144 * C_IN;              // 13824
    if (i < NX) {
        int q = i / HW, hw = i - q * HW;     // q = n*24+kp
        int n = q / 24, kp = q - n * 24;
        const float* xp = x + ((size_t)(n * C_IN + kp * 4)) * HW + hw;
        int a0 = ((int)(xp[0] - 128.f)) & 0xFF;
        int a1 = ((int)(xp[HW] - 128.f)) & 0xFF;
        int a2 = ((int)(xp[2 * HW] - 128.f)) & 0xFF;
        int a3 = ((int)(xp[3 * HW] - 128.f)) & 0xFF;
        g_xp[i] = a0 | (a1 << 8) | (a2 << 16) | (a3 << 24);
    } else if (i < NX + NWE) {
        int j = i - NX;                      // j = kp*576+oc
        int kp = j / C_EXP, oc = j - kp * C_EXP;
        const float* w = we + oc * C_IN + kp * 4;
        int b0 = ((int)w[0]) & 0xFF, b1 = ((int)w[1]) & 0xFF;
        int b2 = ((int)w[2]) & 0xFF, b3 = ((int)w[3]) & 0xFF;
        g_wpe[j] = b0 | (b1 << 8) | (b2 << 16) | (b3 << 24);
    } else if (i < NX + NWE + NWP) {
        int j = i - NX - NWE;                // j = kp*96+oc
        int kp = j / C_IN, oc = j - kp * C_IN;
        const float* w = wp + oc * C_EXP + kp * 4;
        int b0 = ((int)w[0]) & 0xFF, b1 = ((int)w[1]) & 0xFF;
        int b2 = ((int)w[2]) & 0xFF, b3 = ((int)w[3]) & 0xFF;
        g_wpp[j] = b0 | (b1 << 8) | (b2 << 16) | (b3 << 24);
    }
}

// ---------------------------------------------------------------------------
// K1: expand 1x1 conv as int8 dp4a GEMM (M=50176, N=576, K=96). A and B are
// pre-packed; loads are straight int copies. Stores e-128 (shifted domain).
// ---------------------------------------------------------------------------
__global__ __launch_bounds__(256) void k_expand(const float* __restrict__ bias) {
    __shared__ int As[24][64];   // [kp][m]
    __shared__ int Bs[24][64];   // [kp][oc]
    const int mBase = blockIdx.x * 64;
    const int nBase = blockIdx.y * 64;
    const int tid = threadIdx.x;
    const int n0 = mBase / HW;
    const int hw0 = mBase - n0 * HW;

    for (int i = tid; i < 24 * 64; i += 256) {
        int kp = i >> 6, m = i & 63;
        int hw = hw0 + m, n = n0;
        if (hw >= HW) { hw -= HW; n++; }
        As[kp][m] = g_xp[(n * 24 + kp) * HW + hw];
    }
    for (int i = tid; i < 24 * 64; i += 256) {
        int kp = i >> 6, oc = i & 63;
        Bs[kp][oc] = g_wpe[kp * C_EXP + nBase + oc];
    }
    __syncthreads();

    const int tx = tid & 15;   // m lane
    const int ty = tid >> 4;   // n group
    int acc[4][4];
#pragma unroll
    for (int i = 0; i < 4; i++)
#pragma unroll
        for (int j = 0; j < 4; j++) acc[i][j] = 0;

#pragma unroll
    for (int kp = 0; kp < 24; kp++) {
        int av[4];
#pragma unroll
        for (int i = 0; i < 4; i++) av[i] = As[kp][tx + 16 * i];
        int4 bb = *(const int4*)&Bs[kp][ty * 4];
        int bv[4] = {bb.x, bb.y, bb.z, bb.w};
#pragma unroll
        for (int i = 0; i < 4; i++)
#pragma unroll
            for (int j = 0; j < 4; j++)
                acc[i][j] = __dp4a(av[i], bv[j], acc[i][j]);
    }

#pragma unroll
    for (int i = 0; i < 4; i++) {
        int m = tx + 16 * i;
        int hw = hw0 + m, n = n0;
        if (hw >= HW) { hw -= HW; n++; }
#pragma unroll
        for (int j = 0; j < 4; j++) {
            int oc = nBase + ty * 4 + j;
            float a = (float)acc[i][j] + bias[oc];
            float deq = a * (0.05f * 0.01f);                   // S_IN * W_SCALE
            float ev = clamp255(hswish(deq) * 25.f + 128.f);   // 1/S1=25, Z1=128
            g_e[((size_t)(n * C_EXP + oc)) * HW + hw] = ev - 128.f;  // pre-shifted
        }
    }
}

// ---------------------------------------------------------------------------
// K2: depthwise 5x5 (pad 2) + hardswish + requant, fused global-average pool.
// Stores d-128 (shifted domain); pool is mean of shifted values.
// ---------------------------------------------------------------------------
__global__ __launch_bounds__(128) void k_dw(const float* __restrict__ w,
                                            const float* __restrict__ bias) {
    __shared__ float tile[32][33];
    __shared__ __align__(16) float outp[HW];
    __shared__ float wgt[25];
    __shared__ float wsum[4];
    const int nc = blockIdx.x;           // n*576 + c
    const int c = nc % C_EXP;
    const int tid = threadIdx.x;
    const float* ep = g_e + (size_t)nc * HW;   // already e-128 (halo = 0)

    // zero padded tile
    for (int i = tid; i < 32 * 33; i += 128) ((float*)tile)[i] = 0.f;
    if (tid < 25) wgt[tid] = w[c * 25 + tid];
    const float bv = bias[c];
    __syncthreads();

    // coalesced float4 load + scatter into padded tile
    for (int t = tid; t < 196; t += 128) {
        float4 v = ((const float4*)ep)[t];
        int lin = 4 * t;
        int r = lin / HDIM;
        int col = lin - HDIM * r;
        float vv[4] = {v.x, v.y, v.z, v.w};
#pragma unroll
        for (int u = 0; u < 4; u++) {
            tile[r + 2][col + 2] = vv[u];
            col++;
            if (col == HDIM) { col = 0; r++; }
        }
    }
    __syncthreads();

    float lsum = 0.f;
    if (tid < 112) {
        const int row = tid >> 2;          // 0..27
        const int wb = (tid & 3) * 7;      // 0,7,14,21
        float acc[7];
#pragma unroll
        for (int j = 0; j < 7; j++) acc[j] = bv;
#pragma unroll
        for (int kh = 0; kh < 5; kh++) {
            float rr[11];
#pragma unroll
            for (int q = 0; q < 11; q++) rr[q] = tile[row + kh][wb + q];
#pragma unroll
            for (int kw = 0; kw < 5; kw++) {
                float wv = wgt[kh * 5 + kw];
#pragma unroll
                for (int j = 0; j < 7; j++) acc[j] = fmaf(rr[j + kw], wv, acc[j]);
            }
        }
#pragma unroll
        for (int j = 0; j < 7; j++) {
            float deq = acc[j] * (0.04f * 0.01f);                // S1 * W_SCALE
            float dv = clamp255(hswish(deq) * 25.f + 128.f);     // 1/S2=25, Z2=128
            float dvs = dv - 128.f;                              // shifted domain
            outp[row * HDIM + wb + j] = dvs;
            lsum += dvs;
        }
    }
    for (int o = 16; o > 0; o >>= 1) lsum += __shfl_down_sync(0xFFFFFFFFu, lsum, o);
    if ((tid & 31) == 0) wsum[tid >> 5] = lsum;
    __syncthreads();

    float* dp = g_d + (size_t)nc * HW;
    for (int i = tid; i < HW / 4; i += 128)
        *(float4*)(dp + 4 * i) = *(const float4*)(outp + 4 * i);
    if (tid == 0)
        g_pool[nc] = (wsum[0] + wsum[1] + wsum[2] + wsum[3]) * (1.f / 784.f);
}

// ---------------------------------------------------------------------------
// K3a: SE fc1. One warp per (n, o) output: grid (64, 18) x 8 warps = 9216
// warps chip-wide (latency fully hidden). 576-long dot, unrolled 18 deep.
// ---------------------------------------------------------------------------
__global__ __launch_bounds__(256) void k_se1(const float* __restrict__ w1,
                                             const float* __restrict__ b1) {
    __shared__ float ps[C_EXP];
    const int n = blockIdx.x;
    const int tid = threadIdx.x;
    for (int i = tid; i < C_EXP; i += 256)
        ps[i] = g_pool[n * C_EXP + i];             // already shifted by Z2
    __syncthreads();
    const int wid = tid >> 5, lane = tid & 31;
    const int o = blockIdx.y * 8 + wid;            // 0..143
    const float* wr = w1 + o * C_EXP;
    float acc = 0.f;
#pragma unroll
    for (int it = 0; it < 18; it++) {
        int k = lane + 32 * it;
        acc = fmaf(ps[k], wr[k], acc);
    }
    for (int off = 16; off > 0; off >>= 1) acc += __shfl_down_sync(0xFFFFFFFFu, acc, off);
    if (lane == 0) {
        acc += b1[o];
        float deq = acc * (0.04f * 0.01f);         // S2 * W_SCALE
        float g1 = clamp255(deq * (float)(1.0 / 0.03) + 128.f);
        g_g1[n * C_SE + o] = g1 - 128.f;
    }
}

// ---------------------------------------------------------------------------
// K3b: SE fc2 + hardsigmoid -> gate multiplier. One warp per (n, o):
// grid (64, 72) x 8 warps = 36864 warps.
// ---------------------------------------------------------------------------
__global__ __launch_bounds__(256) void k_se2(const float* __restrict__ w2,
                                             const float* __restrict__ b2) {
    __shared__ float g1s[C_SE];
    const int n = blockIdx.x;
    const int tid = threadIdx.x;
    for (int i = tid; i < C_SE; i += 256)
        g1s[i] = g_g1[n * C_SE + i];
    __syncthreads();
    const int wid = tid >> 5, lane = tid & 31;
    const int o = blockIdx.y * 8 + wid;            // 0..575
    const float* wr = w2 + o * C_SE;
    float acc = 0.f;
#pragma unroll
    for (int it = 0; it < 5; it++) {
        int k = lane + 32 * it;
        if (k < C_SE) acc = fmaf(g1s[k], wr[k], acc);
    }
    for (int off = 16; off > 0; off >>= 1) acc += __shfl_down_sync(0xFFFFFFFFu, acc, off);
    if (lane == 0) {
        acc += b2[o];
        float deq = acc * (0.03f * 0.01f);         // S_SE1 * W_SCALE
        float hsg = fminf(fmaxf(deq + 3.f, 0.f), 6.f) * (1.f / 6.f);
        float g2 = clamp255(hsg * 255.f);          // 1/S_SE2=255
        g_gmul[n * C_EXP + o] = g2 * (float)(1.0 / 255.0);  // S_SE2*S2/S_MUL
    }
}

// ---------------------------------------------------------------------------
// K3.5: build the packed gated A matrix for the project GEMM.
// a = clip(gmul*dshift,-128,127) ~= ah + al/128 exact to 1/256 (dshift=d-128).
// ---------------------------------------------------------------------------
__global__ __launch_bounds__(224) void k_gate() {
    const int b = blockIdx.x;              // n*144 + kp
    const int n = b / 144, kp = b - n * 144;
    const int t = threadIdx.x;
    if (t >= 196) return;
    const int hw = 4 * t;
    const float* dbase = g_d + ((size_t)(n * C_EXP + kp * 4)) * HW + hw;
    float gm[4];
    float4 dv[4];
#pragma unroll
    for (int u = 0; u < 4; u++) {
        gm[u] = g_gmul[n * C_EXP + kp * 4 + u];
        dv[u] = *(const float4*)(dbase + (size_t)u * HW);
    }
    int outH[4], outL[4];
#pragma unroll
    for (int e = 0; e < 4; e++) {
        int ph = 0, pl = 0;
#pragma unroll
        for (int u = 0; u < 4; u++) {
            float d = (&dv[u].x)[e];                     // already d-128
            float a = fminf(fmaxf(gm[u] * d, -128.f), 127.f);
            float ahf = rintf(a);
            int ah = (int)ahf;
            int al = (int)rintf((a - ahf) * 128.f);
            ph |= (ah & 0xFF) << (8 * u);
            pl |= (al & 0xFF) << (8 * u);
        }
        outH[e] = ph; outL[e] = pl;
    }
    *(int4*)(g_ah + (size_t)b * HW + hw) = make_int4(outH[0], outH[1], outH[2], outH[3]);
    *(int4*)(g_al + (size_t)b * HW + hw) = make_int4(outL[0], outL[1], outL[2], outL[3]);
}

// ---------------------------------------------------------------------------
// K4: project 1x1 GEMM (M=50176, N=96, K=576) + residual add.
// 128 threads, tile 64m x 48oc (grid 784 x 2). B fully resident in smem,
// A (hi/lo) streamed via cp.async 2-stage double buffer. 9 K-tiles of 64.
// ---------------------------------------------------------------------------
__global__ __launch_bounds__(128) void k_proj(const float* __restrict__ x,
                                              const float* __restrict__ bias,
                                              float* __restrict__ out) {
    __shared__ int Bs[144 * 48];           // [kp][oc]  27.6 KB
    __shared__ int AsH[2][16 * 64];        // [buf][kp][m] 8 KB
    __shared__ int AsL[2][16 * 64];        // 8 KB
    const int mBase = blockIdx.x * 64;
    const int ocBase = blockIdx.y * 48;
    const int tid = threadIdx.x;
    const int tx = tid & 15;               // m lane: m = tx + 16*i
    const int ty = tid >> 4;               // 0..7: oc = ocBase + ty*6 + j
    const int n0 = mBase / HW;
    const int hw0 = mBase - n0 * HW;

    // Resident B
    for (int i = tid; i < 144 * 48; i += 128) {
        int kp = i / 48, oc = i - kp * 48;
        Bs[i] = g_wpp[kp * C_IN + ocBase + oc];
    }

    // Per-thread A source offsets (8 (kp,m) pairs per tile)
    int pOff[8];
#pragma unroll
    for (int p = 0; p < 8; p++) {
        int idx = tid + 128 * p;
        int kp = idx >> 6, m = idx & 63;
        int hw = hw0 + m, n = n0;
        if (hw >= HW) { hw -= HW; n++; }
        pOff[p] = (n * 144 + kp) * HW + hw;
    }
    const unsigned sH = (unsigned)__cvta_generic_to_shared(&AsH[0][0]);
    const unsigned sL = (unsigned)__cvta_generic_to_shared(&AsL[0][0]);

    // Prime tile 0
#pragma unroll
    for (int p = 0; p < 8; p++) {
        unsigned d = (tid + 128 * p) * 4u;
        CPA4(sH + d, g_ah + pOff[p]);
        CPA4(sL + d, g_al + pOff[p]);
    }
    asm volatile("cp.async.commit_group;");

    int accH[4][6] = {};
    int accL[4][6] = {};

    for (int t = 0; t < 9; t++) {
        const int buf = t & 1;
        if (t < 8) {
            const int nbuf = buf ^ 1;
            const int adv = (t + 1) * 16 * HW;
#pragma unroll
            for (int p = 0; p < 8; p++) {
                unsigned d = (nbuf * 1024 + tid + 128 * p) * 4u;
                CPA4(sH + d, g_ah + pOff[p] + adv);
                CPA4(sL + d, g_al + pOff[p] + adv);
            }
            asm volatile("cp.async.commit_group;");
            asm volatile("cp.async.wait_group 1;");
        } else {
            asm volatile("cp.async.wait_group 0;");
        }
        __syncthreads();

        const int* AH = AsH[buf];
        const int* AL = AsL[buf];
        const int kbase = 16 * t;
#pragma unroll
        for (int kp = 0; kp < 16; kp++) {
            int avh[4], avl[4], bv[6];
#pragma unroll
            for (int i = 0; i < 4; i++) {
                avh[i] = AH[kp * 64 + tx + 16 * i];
                avl[i] = AL[kp * 64 + tx + 16 * i];
            }
#pragma unroll
            for (int j = 0; j < 6; j++) bv[j] = Bs[(kbase + kp) * 48 + ty * 6 + j];
#pragma unroll
            for (int i = 0; i < 4; i++)
#pragma unroll
                for (int j = 0; j < 6; j++) {
                    accH[i][j] = __dp4a(avh[i], bv[j], accH[i][j]);
                    accL[i][j] = __dp4a(avl[i], bv[j], accL[i][j]);
                }
        }
        __syncthreads();
    }

#pragma unroll
    for (int i = 0; i < 4; i++) {
        int m = tx + 16 * i;
        int hw = hw0 + m, n = n0;
        if (hw >= HW) { hw -= HW; n++; }
#pragma unroll
        for (int j = 0; j < 6; j++) {
            int oc = ocBase + ty * 6 + j;
            float a = (float)accH[i][j] + (float)accL[i][j] * 0.0078125f + bias[oc];
            float deq = a * (0.04f * 0.01f);              // S_MUL * W_SCALE
            float p = clamp255(deq * 20.f + 128.f);       // 1/S3=20, Z3=128
            size_t idx = ((size_t)(n * C_IN + oc)) * HW + hw;
            float xv = x[idx];
            // (x-128)*(S_IN/S_OUT) + (p-128)*(S3/S_OUT) + Z_OUT, both ratios = 5/6
            out[idx] = clamp255(((xv - 128.f) + (p - 128.f)) * (0.05f / 0.06f) + 128.f);
        }
    }
}

// ---------------------------------------------------------------------------
extern "C" void kernel_launch(void* const* d_in, const int* in_sizes, int n_in,
                              void* d_out, int out_size) {
    const float* x      = (const float*)d_in[0];
    const float* w_exp  = (const float*)d_in[1];
    const float* b_exp  = (const float*)d_in[2];
    const float* w_dw   = (const float*)d_in[3];
    const float* b_dw   = (const float*)d_in[4];
    const float* w_se1  = (const float*)d_in[5];
    const float* b_se1  = (const float*)d_in[6];
    const float* w_se2  = (const float*)d_in[7];
    const float* b_se2  = (const float*)d_in[8];
    const float* w_proj = (const float*)d_in[9];
    const float* b_proj = (const float*)d_in[10];
    float* out = (float*)d_out;

    (void)in_sizes; (void)n_in; (void)out_size;

    const int PACK_TOTAL = N_IMG * 24 * HW + 24 * C_EXP + 144 * C_IN;
    k_pack<<<(PACK_TOTAL + 255) / 256, 256>>>(x, w_exp, w_proj);
    k_expand<<<dim3(784, 9), 256>>>(b_exp);
    k_dw<<<N_IMG * C_EXP, 128>>>(w_dw, b_dw);
    k_se1<<<dim3(N_IMG, 18), 256>>>(w_se1, b_se1);
    k_se2<<<dim3(N_IMG, 72), 256>>>(w_se2, b_se2);
    k_gate<<<N_IMG * 144, 224>>>();
    k_proj<<<dim3(784, 2), 128>>>(x, b_proj, out);
}

// round 14
// speedup vs baseline: 2.6544x; 1.0675x over previous
#include <cuda_runtime.h>
#include <cstdint>

// Problem constants
#define N_IMG 64
#define C_IN 96
#define C_EXP 576
#define C_SE 144
#define KP4 144          // C_EXP / 4 channel groups
#define HW 784
#define HDIM 28

// Scratch (device globals: allocation-free, graph-capturable)
__device__ uint2 g_e16[(size_t)N_IMG * KP4 * HW];   // expand out, (e-128)*128 int16, 4ch packed
__device__ uint2 g_d16[(size_t)N_IMG * KP4 * HW];   // dw out, (d-128)*128 int16, 4ch packed
__device__ float g_pool[N_IMG * C_EXP];             // global avg pool of (d-128)
__device__ float g_g1[N_IMG * C_SE];                // SE fc1 output - 128
__device__ float4 g_gmul4[N_IMG * KP4];             // SE gate multiplier, 4ch packed

__device__ int g_xp[N_IMG * 24 * HW];               // packed x-128 int8x4
__device__ int g_wpe[24 * C_EXP];                   // packed w_exp, [kp*576+oc]
__device__ __align__(16) int g_wpp[144 * C_IN];     // packed w_proj, [kp*96+oc]

__device__ __forceinline__ float clamp255(float v) { return fminf(fmaxf(v, 0.f), 255.f); }
__device__ __forceinline__ float hswish(float v) {
    return v * (fminf(fmaxf(v + 3.f, 0.f), 6.f) * (1.f / 6.f));
}
__device__ __forceinline__ unsigned pack2(short a, short b) {
    return ((unsigned)(unsigned short)a) | (((unsigned)(unsigned short)b) << 16);
}

#define CPA16(dst_u32, src_ptr) \
    asm volatile("cp.async.cg.shared.global [%0], [%1], 16;" ::"r"(dst_u32), "l"(src_ptr))

// ---------------------------------------------------------------------------
// K0: one-time packing of x (int8x4) and both GEMM weight matrices.
// ---------------------------------------------------------------------------
__global__ __launch_bounds__(256) void k_pack(const float* __restrict__ x,
                                              const float* __restrict__ we,
                                              const float* __restrict__ wp) {
    const int i = blockIdx.x * 256 + threadIdx.x;
    const int NX = N_IMG * 24 * HW;
    const int NWE = 24 * C_EXP;
    const int NWP = 144 * C_IN;
    if (i < NX) {
        int q = i / HW, hw = i - q * HW;
        int n = q / 24, kp = q - n * 24;
        const float* xp = x + ((size_t)(n * C_IN + kp * 4)) * HW + hw;
        int a0 = ((int)(xp[0] - 128.f)) & 0xFF;
        int a1 = ((int)(xp[HW] - 128.f)) & 0xFF;
        int a2 = ((int)(xp[2 * HW] - 128.f)) & 0xFF;
        int a3 = ((int)(xp[3 * HW] - 128.f)) & 0xFF;
        g_xp[i] = a0 | (a1 << 8) | (a2 << 16) | (a3 << 24);
    } else if (i < NX + NWE) {
        int j = i - NX;
        int kp = j / C_EXP, oc = j - kp * C_EXP;
        const float* w = we + oc * C_IN + kp * 4;
        int b0 = ((int)w[0]) & 0xFF, b1 = ((int)w[1]) & 0xFF;
        int b2 = ((int)w[2]) & 0xFF, b3 = ((int)w[3]) & 0xFF;
        g_wpe[j] = b0 | (b1 << 8) | (b2 << 16) | (b3 << 24);
    } else if (i < NX + NWE + NWP) {
        int j = i - NX - NWE;
        int kp = j / C_IN, oc = j - kp * C_IN;
        const float* w = wp + oc * C_EXP + kp * 4;
        int b0 = ((int)w[0]) & 0xFF, b1 = ((int)w[1]) & 0xFF;
        int b2 = ((int)w[2]) & 0xFF, b3 = ((int)w[3]) & 0xFF;
        g_wpp[j] = b0 | (b1 << 8) | (b2 << 16) | (b3 << 24);
    }
}

// ---------------------------------------------------------------------------
// K1: expand 1x1 dp4a GEMM (M=50176, N=576, K=96). Epilogue stores
// (e-128)*128 as int16, 4 consecutive oc packed per uint2 (coalesced).
// ---------------------------------------------------------------------------
__global__ __launch_bounds__(256) void k_expand(const float* __restrict__ bias) {
    __shared__ int As[24][64];
    __shared__ int Bs[24][64];
    const int mBase = blockIdx.x * 64;
    const int nBase = blockIdx.y * 64;
    const int tid = threadIdx.x;
    const int n0 = mBase / HW;
    const int hw0 = mBase - n0 * HW;

    for (int i = tid; i < 24 * 64; i += 256) {
        int kp = i >> 6, m = i & 63;
        int hw = hw0 + m, n = n0;
        if (hw >= HW) { hw -= HW; n++; }
        As[kp][m] = g_xp[(n * 24 + kp) * HW + hw];
    }
    for (int i = tid; i < 24 * 64; i += 256) {
        int kp = i >> 6, oc = i & 63;
        Bs[kp][oc] = g_wpe[kp * C_EXP + nBase + oc];
    }
    __syncthreads();

    const int tx = tid & 15;
    const int ty = tid >> 4;
    int acc[4][4];
#pragma unroll
    for (int i = 0; i < 4; i++)
#pragma unroll
        for (int j = 0; j < 4; j++) acc[i][j] = 0;

#pragma unroll
    for (int kp = 0; kp < 24; kp++) {
        int av[4];
#pragma unroll
        for (int i = 0; i < 4; i++) av[i] = As[kp][tx + 16 * i];
        int4 bb = *(const int4*)&Bs[kp][ty * 4];
        int bv[4] = {bb.x, bb.y, bb.z, bb.w};
#pragma unroll
        for (int i = 0; i < 4; i++)
#pragma unroll
            for (int j = 0; j < 4; j++)
                acc[i][j] = __dp4a(av[i], bv[j], acc[i][j]);
    }

    const int kpE = (nBase >> 2) + ty;      // channel group index (4 oc)
#pragma unroll
    for (int i = 0; i < 4; i++) {
        int m = tx + 16 * i;
        int hw = hw0 + m, n = n0;
        if (hw >= HW) { hw -= HW; n++; }
        short s[4];
#pragma unroll
        for (int j = 0; j < 4; j++) {
            int oc = nBase + ty * 4 + j;
            float a = (float)acc[i][j] + bias[oc];
            float deq = a * (0.05f * 0.01f);                   // S_IN * W_SCALE
            float ev = clamp255(hswish(deq) * 25.f + 128.f);   // 1/S1=25, Z1=128
            s[j] = (short)__float2int_rn((ev - 128.f) * 128.f);
        }
        uint2 pv;
        pv.x = pack2(s[0], s[1]);
        pv.y = pack2(s[2], s[3]);
        g_e16[((size_t)(n * KP4 + kpE)) * HW + hw] = pv;
    }
}

// ---------------------------------------------------------------------------
// K2: depthwise 5x5 (pad 2) + hardswish + requant + pool, 4 channels/block.
// Input/output int16 4-ch packed (fully coalesced uint2). 448 work items
// (4ch x 28row x 4 col-groups of 7), 2 per thread.
// ---------------------------------------------------------------------------
__global__ __launch_bounds__(256) void k_dw(const float* __restrict__ w,
                                            const float* __restrict__ bias) {
    __shared__ float tile[4 * 1064];          // 4 padded 32x33 planes, stride 1064
    __shared__ short out16[HW * 4];           // [hw][cl]
    __shared__ float wgt[100];
    __shared__ float bsm[4];
    __shared__ float wsum[8][4];
    const int b = blockIdx.x;                 // n*144 + kp
    const int n = b / KP4, kp = b - n * KP4;
    const int tid = threadIdx.x;
    const uint2* ep = g_e16 + (size_t)b * HW;

    for (int i = tid; i < 4 * 1064; i += 256) tile[i] = 0.f;
    if (tid < 100) wgt[tid] = w[kp * 100 + tid];
    if (tid < 4) bsm[tid] = bias[kp * 4 + tid];
    __syncthreads();

    for (int t = tid; t < HW; t += 256) {
        uint2 v = ep[t];
        int r = t / HDIM, c = t - HDIM * r;
        int base = (r + 2) * 33 + (c + 2);
        tile[0 * 1064 + base] = (float)((short)(v.x & 0xFFFF)) * (1.f / 128.f);
        tile[1 * 1064 + base] = (float)((short)(v.x >> 16)) * (1.f / 128.f);
        tile[2 * 1064 + base] = (float)((short)(v.y & 0xFFFF)) * (1.f / 128.f);
        tile[3 * 1064 + base] = (float)((short)(v.y >> 16)) * (1.f / 128.f);
    }
    __syncthreads();

    float lsum = 0.f;
#pragma unroll
    for (int p = 0; p < 2; p++) {
        int wk = tid + 256 * p;
        if (wk < 448) {
            int cl = wk & 3;
            int slot = wk >> 2;
            int row = slot >> 2;
            int wb = (slot & 3) * 7;
            const float* tb = tile + cl * 1064;
            const float* wg = wgt + cl * 25;
            float acc[7];
            float bv = bsm[cl];
#pragma unroll
            for (int j = 0; j < 7; j++) acc[j] = bv;
#pragma unroll
            for (int kh = 0; kh < 5; kh++) {
                float rr[11];
#pragma unroll
                for (int q = 0; q < 11; q++) rr[q] = tb[(row + kh) * 33 + wb + q];
#pragma unroll
                for (int kw = 0; kw < 5; kw++) {
                    float wv = wg[kh * 5 + kw];
#pragma unroll
                    for (int j = 0; j < 7; j++) acc[j] = fmaf(rr[j + kw], wv, acc[j]);
                }
            }
#pragma unroll
            for (int j = 0; j < 7; j++) {
                float deq = acc[j] * (0.04f * 0.01f);                // S1 * W_SCALE
                float dv = clamp255(hswish(deq) * 25.f + 128.f);     // 1/S2, Z2
                float dvs = dv - 128.f;
                out16[(row * HDIM + wb + j) * 4 + cl] = (short)__float2int_rn(dvs * 128.f);
                lsum += dvs;
            }
        }
    }
    // per-channel reduce: lanes = cl mod 4 share channel (both items same cl)
    lsum += __shfl_xor_sync(0xFFFFFFFFu, lsum, 4);
    lsum += __shfl_xor_sync(0xFFFFFFFFu, lsum, 8);
    lsum += __shfl_xor_sync(0xFFFFFFFFu, lsum, 16);
    if ((tid & 31) < 4) wsum[tid >> 5][tid & 3] = lsum;
    __syncthreads();

    uint2* dp = g_d16 + (size_t)b * HW;
    const uint2* o2 = (const uint2*)out16;
    for (int t = tid; t < HW; t += 256) dp[t] = o2[t];
    if (tid < 4) {
        float tot = 0.f;
#pragma unroll
        for (int i = 0; i < 8; i++) tot += wsum[i][tid];
        g_pool[n * C_EXP + kp * 4 + tid] = tot * (1.f / 784.f);
    }
}

// ---------------------------------------------------------------------------
// K3a: SE fc1, one warp per (n,o). grid (64,18) x 8 warps.
// ---------------------------------------------------------------------------
__global__ __launch_bounds__(256) void k_se1(const float* __restrict__ w1,
                                             const float* __restrict__ b1) {
    __shared__ float ps[C_EXP];
    const int n = blockIdx.x;
    const int tid = threadIdx.x;
    for (int i = tid; i < C_EXP; i += 256)
        ps[i] = g_pool[n * C_EXP + i];
    __syncthreads();
    const int wid = tid >> 5, lane = tid & 31;
    const int o = blockIdx.y * 8 + wid;
    const float* wr = w1 + o * C_EXP;
    float acc = 0.f;
#pragma unroll
    for (int it = 0; it < 18; it++) {
        int k = lane + 32 * it;
        acc = fmaf(ps[k], wr[k], acc);
    }
    for (int off = 16; off > 0; off >>= 1) acc += __shfl_down_sync(0xFFFFFFFFu, acc, off);
    if (lane == 0) {
        acc += b1[o];
        float deq = acc * (0.04f * 0.01f);
        float g1 = clamp255(deq * (float)(1.0 / 0.03) + 128.f);
        g_g1[n * C_SE + o] = g1 - 128.f;
    }
}

// ---------------------------------------------------------------------------
// K3b: SE fc2 + hardsigmoid -> gate multiplier. grid (64,72) x 8 warps.
// ---------------------------------------------------------------------------
__global__ __launch_bounds__(256) void k_se2(const float* __restrict__ w2,
                                             const float* __restrict__ b2) {
    __shared__ float g1s[C_SE];
    const int n = blockIdx.x;
    const int tid = threadIdx.x;
    for (int i = tid; i < C_SE; i += 256)
        g1s[i] = g_g1[n * C_SE + i];
    __syncthreads();
    const int wid = tid >> 5, lane = tid & 31;
    const int o = blockIdx.y * 8 + wid;
    const float* wr = w2 + o * C_SE;
    float acc = 0.f;
#pragma unroll
    for (int it = 0; it < 5; it++) {
        int k = lane + 32 * it;
        if (k < C_SE) acc = fmaf(g1s[k], wr[k], acc);
    }
    for (int off = 16; off > 0; off >>= 1) acc += __shfl_down_sync(0xFFFFFFFFu, acc, off);
    if (lane == 0) {
        acc += b2[o];
        float deq = acc * (0.03f * 0.01f);
        float hsg = fminf(fmaxf(deq + 3.f, 0.f), 6.f) * (1.f / 6.f);
        float g2 = clamp255(hsg * 255.f);
        ((float*)g_gmul4)[n * C_EXP + o] = g2 * (float)(1.0 / 255.0);
    }
}

// ---------------------------------------------------------------------------
// K4: fused SE-gate + project GEMM (M=50176, N=96, K=576) + residual.
// 256 threads, tile 64m x 96oc, 9 K-tiles of 64. Gate+hi/lo split computed
// in registers (prefetched 1 tile ahead) -> smem; B streamed via cp.async
// double buffer. a = gmul*d ~= ah + al/128 (dual dp4a accumulation).
// ---------------------------------------------------------------------------
__global__ __launch_bounds__(256) void k_proj(const float* __restrict__ x,
                                              const float* __restrict__ bias,
                                              float* __restrict__ out) {
    __shared__ int AsH[16][64];                 // 4 KB
    __shared__ int AsL[16][64];                 // 4 KB
    __shared__ __align__(16) int Bs[2][16 * 96];  // 12 KB
    const int mBase = blockIdx.x * 64;
    const int tid = threadIdx.x;
    const int tx = tid & 15;                    // m lane: m = tx + 16*i
    const int ty = tid >> 4;                    // 0..15: oc = ty*6 + j
    const int n0 = mBase / HW;
    const int hw0 = mBase - n0 * HW;

    // per-item constants (4 items: (kp_l, m) pairs)
    int srcOff[4], gmOff[4];
#pragma unroll
    for (int p = 0; p < 4; p++) {
        int idx = tid + 256 * p;
        int kpl = idx >> 6, m = idx & 63;
        int hw = hw0 + m, n = n0;
        if (hw >= HW) { hw -= HW; n++; }
        srcOff[p] = (n * KP4 + kpl) * HW + hw;
        gmOff[p] = n * KP4 + kpl;
    }

    // prime A regs (tile 0) and B (tile 0) via cp.async
    uint2 curD[4];
    float4 curG[4];
#pragma unroll
    for (int p = 0; p < 4; p++) {
        curD[p] = g_d16[srcOff[p]];
        curG[p] = g_gmul4[gmOff[p]];
    }
    {
        unsigned sB = (unsigned)__cvta_generic_to_shared(&Bs[0][0]);
        const int4* src = (const int4*)g_wpp;
        for (int i = tid; i < 384; i += 256)
            CPA16(sB + i * 16u, src + i);
        asm volatile("cp.async.commit_group;");
    }

    int accH[4][6] = {};
    int accL[4][6] = {};

    for (int t = 0; t < 9; t++) {
        __syncthreads();   // previous mainloop done reading AsH/AsL
        // gate + split + STS for tile t
#pragma unroll
        for (int p = 0; p < 4; p++) {
            int idx = tid + 256 * p;
            int kpl = idx >> 6, m = idx & 63;
            float gs[4] = {curG[p].x * (1.f / 128.f), curG[p].y * (1.f / 128.f),
                           curG[p].z * (1.f / 128.f), curG[p].w * (1.f / 128.f)};
            short ds[4];
            ds[0] = (short)(curD[p].x & 0xFFFF);
            ds[1] = (short)(curD[p].x >> 16);
            ds[2] = (short)(curD[p].y & 0xFFFF);
            ds[3] = (short)(curD[p].y >> 16);
            int ph = 0, pl = 0;
#pragma unroll
            for (int u = 0; u < 4; u++) {
                float a = fminf(fmaxf(gs[u] * (float)ds[u], -128.f), 127.f);
                float ahf = rintf(a);
                int ah = (int)ahf;
                int al = (int)rintf((a - ahf) * 128.f);
                ph |= (ah & 0xFF) << (8 * u);
                pl |= (al & 0xFF) << (8 * u);
            }
            AsH[kpl][m] = ph;
            AsL[kpl][m] = pl;
        }
        // prefetch tile t+1 (A regs + B cp.async)
        if (t < 8) {
            const int adv = (t + 1) * 16 * HW;
            const int gadv = (t + 1) * 16;
#pragma unroll
            for (int p = 0; p < 4; p++) {
                curD[p] = g_d16[srcOff[p] + adv];
                curG[p] = g_gmul4[gmOff[p] + gadv];
            }
            unsigned sB = (unsigned)__cvta_generic_to_shared(&Bs[(t + 1) & 1][0]);
            const int4* src = (const int4*)g_wpp + (t + 1) * 384;
            for (int i = tid; i < 384; i += 256)
                CPA16(sB + i * 16u, src + i);
            asm volatile("cp.async.commit_group;");
            asm volatile("cp.async.wait_group 1;");
        } else {
            asm volatile("cp.async.wait_group 0;");
        }
        __syncthreads();

        const int* B = Bs[t & 1];
#pragma unroll
        for (int kp = 0; kp < 16; kp++) {
            int avh[4], avl[4], bv[6];
#pragma unroll
            for (int i = 0; i < 4; i++) {
                avh[i] = AsH[kp][tx + 16 * i];
                avl[i] = AsL[kp][tx + 16 * i];
            }
#pragma unroll
            for (int j = 0; j < 6; j++) bv[j] = B[kp * 96 + ty * 6 + j];
#pragma unroll
            for (int i = 0; i < 4; i++)
#pragma unroll
                for (int j = 0; j < 6; j++) {
                    accH[i][j] = __dp4a(avh[i], bv[j], accH[i][j]);
                    accL[i][j] = __dp4a(avl[i], bv[j], accL[i][j]);
                }
        }
    }

#pragma unroll
    for (int i = 0; i < 4; i++) {
        int m = tx + 16 * i;
        int hw = hw0 + m, n = n0;
        if (hw >= HW) { hw -= HW; n++; }
#pragma unroll
        for (int j = 0; j < 6; j++) {
            int oc = ty * 6 + j;
            float a = (float)accH[i][j] + (float)accL[i][j] * 0.0078125f + bias[oc];
            float deq = a * (0.04f * 0.01f);              // S_MUL * W_SCALE
            float p = clamp255(deq * 20.f + 128.f);       // 1/S3=20, Z3=128
            size_t idx = ((size_t)(n * C_IN + oc)) * HW + hw;
            float xv = x[idx];
            out[idx] = clamp255(((xv - 128.f) + (p - 128.f)) * (0.05f / 0.06f) + 128.f);
        }
    }
}

// ---------------------------------------------------------------------------
extern "C" void kernel_launch(void* const* d_in, const int* in_sizes, int n_in,
                              void* d_out, int out_size) {
    const float* x      = (const float*)d_in[0];
    const float* w_exp  = (const float*)d_in[1];
    const float* b_exp  = (const float*)d_in[2];
    const float* w_dw   = (const float*)d_in[3];
    const float* b_dw   = (const float*)d_in[4];
    const float* w_se1  = (const float*)d_in[5];
    const float* b_se1  = (const float*)d_in[6];
    const float* w_se2  = (const float*)d_in[7];
    const float* b_se2  = (const float*)d_in[8];
    const float* w_proj = (const float*)d_in[9];
    const float* b_proj = (const float*)d_in[10];
    float* out = (float*)d_out;

    (void)in_sizes; (void)n_in; (void)out_size;

    const int PACK_TOTAL = N_IMG * 24 * HW + 24 * C_EXP + 144 * C_IN;
    k_pack<<<(PACK_TOTAL + 255) / 256, 256>>>(x, w_exp, w_proj);
    k_expand<<<dim3(784, 9), 256>>>(b_exp);
    k_dw<<<N_IMG * KP4, 256>>>(w_dw, b_dw);
    k_se1<<<dim3(N_IMG, 18), 256>>>(w_se1, b_se1);
    k_se2<<<dim3(N_IMG, 72), 256>>>(w_se2, b_se2);
    k_proj<<<784, 256>>>(x, b_proj, out);
}